// round 11
// baseline (speedup 1.0000x reference)
#include <cuda_runtime.h>
#include <math.h>

#define B_DIM   8
#define S_DIM   2048
#define IN_DIM  512
#define OUT_DIM 256
#define G_DIM   8
#define SCHUNK  128     // s values per A chunk (33.5 MB; 2 buffers stay L2-resident)
#define SPAN    64      // recurrence re-anchor interval
#define NCHUNK  (S_DIM / SCHUNK)   // 16

typedef unsigned long long ull;

// Static device scratch (allocation-free)
__device__ float g_xt[B_DIM * S_DIM * OUT_DIM];              // 16.8 MB  LN(x@M^T)
__device__ float g_A[2][SCHUNK * OUT_DIM * OUT_DIM];         // 2x33.5MB A[s][j][i]

// ---------------------------------------------------------------------------
// helpers
// ---------------------------------------------------------------------------
__device__ __forceinline__ unsigned cvt_tf32(float f) {
    unsigned r;
    asm("cvt.rna.tf32.f32 %0, %1;" : "=r"(r) : "f"(f));
    return r;
}

__device__ __forceinline__ void mma_tf32(float* d, const unsigned* a, const unsigned* b) {
    asm volatile(
        "mma.sync.aligned.m16n8k8.row.col.f32.tf32.tf32.f32 "
        "{%0,%1,%2,%3}, {%4,%5,%6,%7}, {%8,%9}, {%0,%1,%2,%3};"
        : "+f"(d[0]), "+f"(d[1]), "+f"(d[2]), "+f"(d[3])
        : "r"(a[0]), "r"(a[1]), "r"(a[2]), "r"(a[3]), "r"(b[0]), "r"(b[1]));
}

__device__ __forceinline__ ull pk2(float lo, float hi) {
    ull r;
    asm("mov.b64 %0, {%1, %2};" : "=l"(r) : "f"(lo), "f"(hi));
    return r;
}
__device__ __forceinline__ void upk2(ull v, float& lo, float& hi) {
    asm("mov.b64 {%0, %1}, %2;" : "=f"(lo), "=f"(hi) : "l"(v));
}
__device__ __forceinline__ ull f2fma(ull a, ull b, ull c) {
    ull d;
    asm("fma.rn.f32x2 %0, %1, %2, %3;" : "=l"(d) : "l"(a), "l"(b), "l"(c));
    return d;
}
__device__ __forceinline__ ull f2add(ull a, ull b) {
    ull d;
    asm("add.rn.f32x2 %0, %1, %2;" : "=l"(d) : "l"(a), "l"(b));
    return d;
}

// ---------------------------------------------------------------------------
// K1: dual GEMM via tf32 mma.sync.  h = x@M^T -> g_xt;  res = x@Wres^T -> out.
// BM=128, BN=64, BK=32, 256 threads / 8 warps (4x2), warp tile 32x32.
// ---------------------------------------------------------------------------
__global__ __launch_bounds__(256) void gemm_mma(const float* __restrict__ x,
                                                const float* __restrict__ Mw,
                                                const float* __restrict__ Wres,
                                                float* __restrict__ resout)
{
    __shared__ __align__(16) unsigned Xs[128][36];   // [m][k], +4 pad
    __shared__ __align__(16) unsigned Ws[64][36];    // [n][k], +4 pad

    const int rowTile = blockIdx.x * 128;
    const int cb      = blockIdx.y;                 // 0..7
    const float* W    = (cb < 4) ? Mw : Wres;
    float*       outp = (cb < 4) ? g_xt : resout;
    const int oc      = (cb & 3) * 64;

    const int tid   = threadIdx.x;
    const int warp  = tid >> 5;
    const int lane  = tid & 31;
    const int warpM = (warp & 3) * 32;
    const int warpN = (warp >> 2) * 32;
    const int q     = lane >> 2;     // 0..7
    const int rr    = lane & 3;      // 0..3

    float acc[2][4][4];
#pragma unroll
    for (int tm = 0; tm < 2; tm++)
#pragma unroll
        for (int tn = 0; tn < 4; tn++)
#pragma unroll
            for (int v = 0; v < 4; v++) acc[tm][tn][v] = 0.0f;

    for (int k0 = 0; k0 < IN_DIM; k0 += 32) {
#pragma unroll
        for (int l = 0; l < 4; l++) {
            int lin = tid + l * 256;
            int r   = lin >> 3;
            int u   = lin & 7;
            float4 f = *(const float4*)&x[(rowTile + r) * IN_DIM + k0 + u * 4];
            uint4 c = make_uint4(cvt_tf32(f.x), cvt_tf32(f.y), cvt_tf32(f.z), cvt_tf32(f.w));
            *(uint4*)&Xs[r][u * 4] = c;
        }
#pragma unroll
        for (int l = 0; l < 2; l++) {
            int lin = tid + l * 256;
            int r   = lin >> 3;
            int u   = lin & 7;
            float4 f = *(const float4*)&W[(oc + r) * IN_DIM + k0 + u * 4];
            uint4 c = make_uint4(cvt_tf32(f.x), cvt_tf32(f.y), cvt_tf32(f.z), cvt_tf32(f.w));
            *(uint4*)&Ws[r][u * 4] = c;
        }
        __syncthreads();

#pragma unroll
        for (int k8 = 0; k8 < 32; k8 += 8) {
            unsigned af[2][4], bf[4][2];
#pragma unroll
            for (int tm = 0; tm < 2; tm++) {
                int r0 = warpM + tm * 16 + q;
                af[tm][0] = Xs[r0][k8 + rr];
                af[tm][1] = Xs[r0 + 8][k8 + rr];
                af[tm][2] = Xs[r0][k8 + rr + 4];
                af[tm][3] = Xs[r0 + 8][k8 + rr + 4];
            }
#pragma unroll
            for (int tn = 0; tn < 4; tn++) {
                int n0 = warpN + tn * 8 + q;
                bf[tn][0] = Ws[n0][k8 + rr];
                bf[tn][1] = Ws[n0][k8 + rr + 4];
            }
#pragma unroll
            for (int tm = 0; tm < 2; tm++)
#pragma unroll
                for (int tn = 0; tn < 4; tn++)
                    mma_tf32(acc[tm][tn], af[tm], bf[tn]);
        }
        __syncthreads();
    }

#pragma unroll
    for (int tm = 0; tm < 2; tm++) {
        int row = rowTile + warpM + tm * 16 + q;
#pragma unroll
        for (int tn = 0; tn < 4; tn++) {
            int col = oc + warpN + tn * 8 + 2 * rr;
            *(float2*)&outp[row * OUT_DIM + col] =
                make_float2(acc[tm][tn][0], acc[tm][tn][1]);
            *(float2*)&outp[(row + 8) * OUT_DIM + col] =
                make_float2(acc[tm][tn][2], acc[tm][tn][3]);
        }
    }
}

// ---------------------------------------------------------------------------
// K2: in-place LayerNorm of g_xt rows (256 wide). One warp per row.
// ---------------------------------------------------------------------------
__global__ __launch_bounds__(256) void ln_kernel(const float* __restrict__ sc,
                                                 const float* __restrict__ bi)
{
    const int warp = threadIdx.x >> 5;
    const int lane = threadIdx.x & 31;
    const int row  = blockIdx.x * 8 + warp;
    float4* h = (float4*)(g_xt + row * OUT_DIM);

    float4 v0 = h[lane];
    float4 v1 = h[32 + lane];
    float sum = v0.x + v0.y + v0.z + v0.w + v1.x + v1.y + v1.z + v1.w;
    float sq  = v0.x*v0.x + v0.y*v0.y + v0.z*v0.z + v0.w*v0.w
              + v1.x*v1.x + v1.y*v1.y + v1.z*v1.z + v1.w*v1.w;
#pragma unroll
    for (int o = 16; o > 0; o >>= 1) {
        sum += __shfl_xor_sync(0xFFFFFFFFu, sum, o);
        sq  += __shfl_xor_sync(0xFFFFFFFFu, sq,  o);
    }
    const float inv = 1.0f / 256.0f;
    float mu  = sum * inv;
    float var = sq * inv - mu * mu;
    float rs  = rsqrtf(var + 1e-5f);

    const float4* s4 = (const float4*)sc;
    const float4* b4 = (const float4*)bi;
    float4 sA = s4[lane], sB = s4[32 + lane];
    float4 bA = b4[lane], bB = b4[32 + lane];

    v0.x = (v0.x - mu) * rs * sA.x + bA.x;
    v0.y = (v0.y - mu) * rs * sA.y + bA.y;
    v0.z = (v0.z - mu) * rs * sA.z + bA.z;
    v0.w = (v0.w - mu) * rs * sA.w + bA.w;
    v1.x = (v1.x - mu) * rs * sB.x + bB.x;
    v1.y = (v1.y - mu) * rs * sB.y + bB.y;
    v1.z = (v1.z - mu) * rs * sB.z + bB.z;
    v1.w = (v1.w - mu) * rs * sB.w + bB.w;
    h[lane] = v0;
    h[32 + lane] = v1;
}

// ---------------------------------------------------------------------------
// K3: fused gen+contract "fat kernel", phase k = 0..NCHUNK.
//   blocks [0,256):   gen chunk k  -> g_A[k&1]        (skipped when k==NCHUNK)
//   blocks [256,512): contract chunk k-1 from g_A[(k-1)&1], s split 128x2(b)
// gen uses the subtraction-free packed recurrence: d += t*c; c += d
// (identical to the 3-term Chebyshev form; t = 2cos(2pi/T)-2 kept separate).
// ---------------------------------------------------------------------------
__global__ __launch_bounds__(256) void fused_gc(const float* __restrict__ P,
                                                float* __restrict__ out,
                                                int k)
{
    __shared__ __align__(16) float2 xp[2][256];

    if (blockIdx.x < 256) {
        // ---------------- gen chunk k ----------------
        if (k >= NCHUNK) return;
        const int i = threadIdx.x;
        const int j = blockIdx.x;
        float* gA = g_A[k & 1];

        int T[8];
        float tt[8];
        const float* Pp = P + (i * OUT_DIM + j) * G_DIM;
        ull p2[4], t2[4];
#pragma unroll
        for (int g = 0; g < 8; g++) {
            T[g] = i * (OUT_DIM * G_DIM) + j * G_DIM + g + 2;    // exact integer
            float sp = sinpif(__fdividef(1.0f, (float)T[g]));
            tt[g] = -4.0f * sp * sp;                              // 2cos(2pi/T)-2
        }
#pragma unroll
        for (int q = 0; q < 4; q++) {
            p2[q] = pk2(Pp[2 * q], Pp[2 * q + 1]);
            t2[q] = pk2(tt[2 * q], tt[2 * q + 1]);
        }

        float* ob = gA + j * OUT_DIM + i;

#pragma unroll
        for (int span = 0; span < SCHUNK / SPAN; span++) {
            const int s0 = k * SCHUNK + span * SPAN;
            float cs[8], ds[8];
#pragma unroll
            for (int g = 0; g < 8; g++) {
                int Tg = T[g];
                int m0 = (s0 < Tg) ? s0 : (s0 % Tg);
                int sm = s0 - 1; if (sm < 0) sm += Tg;
                int m1 = (sm < Tg) ? sm : (sm % Tg);
                float Tf = (float)Tg;
                float c1 = cospif(__fdividef(2.0f * (float)m0, Tf));  // cos @ s0
                float c0 = cospif(__fdividef(2.0f * (float)m1, Tf));  // cos @ s0-1
                cs[g] = c1;
                ds[g] = c1 - c0;
            }
            ull c2v[4], d2[4];
#pragma unroll
            for (int q = 0; q < 4; q++) {
                c2v[q] = pk2(cs[2 * q], cs[2 * q + 1]);
                d2[q]  = pk2(ds[2 * q], ds[2 * q + 1]);
            }
            float* os = ob + (span * SPAN) * (OUT_DIM * OUT_DIM);
#pragma unroll 4
            for (int kk = 0; kk < SPAN; kk++) {
                ull acc = 0ull;
#pragma unroll
                for (int q = 0; q < 4; q++)
                    acc = f2fma(p2[q], c2v[q], acc);
                float lo, hi;
                upk2(acc, lo, hi);
                os[kk * (OUT_DIM * OUT_DIM)] = lo + hi;
#pragma unroll
                for (int q = 0; q < 4; q++) {
                    d2[q]  = f2fma(t2[q], c2v[q], d2[q]);   // d += t*c
                    c2v[q] = f2add(c2v[q], d2[q]);          // c += d
                }
            }
        }
    } else {
        // ---------------- contract chunk k-1 ----------------
        if (k == 0) return;
        const int cid = blockIdx.x - 256;
        const int sl  = cid >> 1;
        const int bh  = cid & 1;
        const int b0  = bh * 4;
        const int s   = (k - 1) * SCHUNK + sl;
        const float* gA = g_A[(k - 1) & 1];
        const int i = threadIdx.x;

        xp[0][i] = make_float2(g_xt[((b0 + 0) * S_DIM + s) * OUT_DIM + i],
                               g_xt[((b0 + 1) * S_DIM + s) * OUT_DIM + i]);
        xp[1][i] = make_float2(g_xt[((b0 + 2) * S_DIM + s) * OUT_DIM + i],
                               g_xt[((b0 + 3) * S_DIM + s) * OUT_DIM + i]);
        __syncthreads();

        ull acc0 = pk2(out[((b0 + 0) * S_DIM + s) * OUT_DIM + i],
                       out[((b0 + 1) * S_DIM + s) * OUT_DIM + i]);   // residual
        ull acc1 = pk2(out[((b0 + 2) * S_DIM + s) * OUT_DIM + i],
                       out[((b0 + 3) * S_DIM + s) * OUT_DIM + i]);

        const float* Ab = gA + sl * (OUT_DIM * OUT_DIM) + i;
        const ulonglong2* x0 = (const ulonglong2*)&xp[0][0];
        const ulonglong2* x1 = (const ulonglong2*)&xp[1][0];

        for (int jb = 0; jb < 256; jb += 16) {
            float av[16];
#pragma unroll
            for (int u = 0; u < 16; u++)
                av[u] = Ab[(jb + u) * OUT_DIM];
#pragma unroll
            for (int u = 0; u < 16; u += 2) {
                ulonglong2 q0 = x0[(jb + u) >> 1];
                ulonglong2 q1 = x1[(jb + u) >> 1];
                ull a0 = pk2(av[u], av[u]);
                ull a1 = pk2(av[u + 1], av[u + 1]);
                acc0 = f2fma(q0.x, a0, acc0);
                acc0 = f2fma(q0.y, a1, acc0);
                acc1 = f2fma(q1.x, a0, acc1);
                acc1 = f2fma(q1.y, a1, acc1);
            }
        }

        float r0, r1, r2, r3;
        upk2(acc0, r0, r1);
        upk2(acc1, r2, r3);
        out[((b0 + 0) * S_DIM + s) * OUT_DIM + i] = r0;
        out[((b0 + 1) * S_DIM + s) * OUT_DIM + i] = r1;
        out[((b0 + 2) * S_DIM + s) * OUT_DIM + i] = r2;
        out[((b0 + 3) * S_DIM + s) * OUT_DIM + i] = r3;
    }
}

// ---------------------------------------------------------------------------
// metadata order: x, M, P, W_res, ln_scale, ln_bias, periods, positions
// ---------------------------------------------------------------------------
extern "C" void kernel_launch(void* const* d_in, const int* in_sizes, int n_in,
                              void* d_out, int out_size)
{
    const float* x    = (const float*)d_in[0];
    const float* Mw   = (const float*)d_in[1];
    const float* P    = (const float*)d_in[2];
    const float* Wres = (const float*)d_in[3];
    const float* sc   = (const float*)d_in[4];
    const float* bi   = (const float*)d_in[5];
    float* out = (float*)d_out;
    (void)in_sizes; (void)n_in; (void)out_size;

    gemm_mma<<<dim3(128, 8), 256>>>(x, Mw, Wres, out);
    ln_kernel<<<2048, 256>>>(sc, bi);
    for (int k = 0; k <= NCHUNK; k++)
        fused_gc<<<512, 256>>>(P, out, k);
}